// round 9
// baseline (speedup 1.0000x reference)
#include <cuda_runtime.h>
#include <cuda_fp16.h>
#include <cstdint>

#define BATCH  4
#define SEQ    2048
#define DMODEL 1024
#define NHEADS 16
#define DK     64
#define MROWS  (BATCH * SEQ)   // 8192

// Q prescale: 1/sqrt(64) * log2(e)  (softmax uses exp2)
#define QSCALE 0.18033688f

// ---------------- scratch (device globals; no runtime allocation) ----------
__device__ __half g_Qf[(size_t)MROWS * DMODEL];   // [B,H,S,DK] fp16 (pre-scaled)
__device__ __half g_Kf[(size_t)MROWS * DMODEL];
__device__ __half g_Vf[(size_t)MROWS * DMODEL];
__device__ __half g_AQ[(size_t)MROWS * DMODEL];   // rounded activations per input
__device__ __half g_AK[(size_t)MROWS * DMODEL];
__device__ __half g_AV[(size_t)MROWS * DMODEL];
__device__ __half g_Af[(size_t)MROWS * DMODEL];   // attn output (final GEMM A)
__device__ __half g_W4[(size_t)4 * DMODEL * DMODEL];  // rounded Wq,Wk,Wv,Wo
__device__ unsigned char g_flags[BATCH * (SEQ / 128) * (SEQ / 64)];  // 2048

// ---------------- helpers ---------------------------------------------------
static __device__ __forceinline__ uint32_t smem_u32(const void* p) {
    uint32_t r;
    asm("{ .reg .u64 t; cvta.to.shared.u64 t, %1; cvt.u32.u64 %0, t; }"
        : "=r"(r) : "l"(p));
    return r;
}

#define CP_ASYNC16(smem_addr, gptr) \
    asm volatile("cp.async.cg.shared.global [%0], [%1], 16;" \
                 :: "r"(smem_addr), "l"(gptr))
#define CP_COMMIT()  asm volatile("cp.async.commit_group;" ::: "memory")
#define CP_WAIT(N)   asm volatile("cp.async.wait_group %0;" :: "n"(N) : "memory")

#define LDSM_X4(r0, r1, r2, r3, addr) \
    asm volatile("ldmatrix.sync.aligned.m8n8.x4.shared.b16 {%0,%1,%2,%3}, [%4];" \
                 : "=r"(r0), "=r"(r1), "=r"(r2), "=r"(r3) : "r"(addr))

#define LDSM_X4_T(r0, r1, r2, r3, addr) \
    asm volatile("ldmatrix.sync.aligned.m8n8.x4.trans.shared.b16 {%0,%1,%2,%3}, [%4];" \
                 : "=r"(r0), "=r"(r1), "=r"(r2), "=r"(r3) : "r"(addr))

#define MMA_F16(c, a, b0v, b1v) \
    asm volatile("mma.sync.aligned.m16n8k16.row.col.f32.f16.f16.f32 " \
                 "{%0,%1,%2,%3}, {%4,%5,%6,%7}, {%8,%9}, {%0,%1,%2,%3};" \
                 : "+f"((c)[0]), "+f"((c)[1]), "+f"((c)[2]), "+f"((c)[3]) \
                 : "r"((a)[0]), "r"((a)[1]), "r"((a)[2]), "r"((a)[3]), \
                   "r"(b0v), "r"(b1v))

static __device__ __forceinline__ uint32_t pack2h(float x, float y) {
    __half2 h = __floats2half2_rn(x, y);
    return *(uint32_t*)&h;
}

// ---------------------------------------------------------------------------
// Fused prep: z=0..2 round activations, z=3..6 round weights, z=7 mask flags
// ---------------------------------------------------------------------------
__global__ __launch_bounds__(256)
void prep(const float* __restrict__ q, const float* __restrict__ k,
          const float* __restrict__ v,
          const float* __restrict__ wq, const float* __restrict__ wk,
          const float* __restrict__ wv, const float* __restrict__ wo,
          const int* __restrict__ mask)
{
    const int z = blockIdx.z;
    const int bx = blockIdx.x;

    if (z < 3) {                       // activations: 8192 blocks each
        const float* src = (z == 0) ? q : (z == 1) ? k : v;
        __half* dst = (z == 0) ? g_AQ : (z == 1) ? g_AK : g_AV;
        int i = bx * 256 + threadIdx.x;
        float4 vv = ((const float4*)src)[i];
        ((uint32_t*)dst)[2 * i]     = pack2h(vv.x, vv.y);
        ((uint32_t*)dst)[2 * i + 1] = pack2h(vv.z, vv.w);
    } else if (z < 7) {                // weights: 1024 blocks each
        if (bx >= DMODEL * DMODEL / 4 / 256) return;
        const int wz = z - 3;
        const float* src = (wz == 0) ? wq : (wz == 1) ? wk : (wz == 2) ? wv : wo;
        __half* dst = g_W4 + (size_t)wz * DMODEL * DMODEL;
        int i = bx * 256 + threadIdx.x;
        float4 vv = ((const float4*)src)[i];
        ((uint32_t*)dst)[2 * i]     = pack2h(vv.x, vv.y);
        ((uint32_t*)dst)[2 * i + 1] = pack2h(vv.z, vv.w);
    } else {                           // mask flags: 2048 blocks
        if (bx >= BATCH * (SEQ / 128) * (SEQ / 64)) return;
        const int kt = bx & 31, qt = (bx >> 5) & 15, b = bx >> 9;
        const int tid = threadIdx.x;
        const int qr = tid >> 1, ch = (tid & 1) * 32;
        const int* row = mask + ((size_t)b * SEQ + qt * 128 + qr) * SEQ + kt * 64 + ch;
        int ok = 1;
#pragma unroll
        for (int i = 0; i < 8; i++) {
            int4 mv = *(const int4*)(row + i * 4);
            ok &= (mv.x != 0) & (mv.y != 0) & (mv.z != 0) & (mv.w != 0);
        }
        int all = __syncthreads_and(ok);
        if (tid == 0) g_flags[bx] = (unsigned char)all;
    }
}

// ---------------------------------------------------------------------------
// GEMM core (single fp16 pass): CTA 128x128, K-tile 64, cp.async double buffer.
// ---------------------------------------------------------------------------
#define KTILES 16
#define TB 16384
#define GSTAGE (2 * TB)
#define GSMEM  (2 * GSTAGE)      // 65536

struct GemmAcc { float a[4][4][4]; };

static __device__ __forceinline__ void gemm_mainloop(
    uint32_t sb, int tid, int wid, int lane, int row0, int col0,
    const __half* Af, const __half* Bf, GemmAcc& acc)
{
    const int wm = wid >> 2, wn = wid & 3;

    auto load_tiles = [&](int kt, int stage) {
        const __half* gA = Af + (size_t)row0 * DMODEL + kt * 64;
        const __half* gB = Bf + (size_t)col0 * DMODEL + kt * 64;
        const uint32_t oA = sb + stage * GSTAGE;
#pragma unroll
        for (int i = 0; i < 4; i++) {
            int cl = tid + 256 * i;
            int r  = cl >> 3, c = cl & 7;
            uint32_t sw = (uint32_t)(r * 128) + ((uint32_t)(c ^ (r & 7)) << 4);
            CP_ASYNC16(oA + sw,      gA + (size_t)r * DMODEL + c * 8);
            CP_ASYNC16(oA + TB + sw, gB + (size_t)r * DMODEL + c * 8);
        }
        CP_COMMIT();
    };

    load_tiles(0, 0);

    for (int t = 0; t < KTILES; t++) {
        const int cur = t & 1;
        if (t + 1 < KTILES) { load_tiles(t + 1, cur ^ 1); CP_WAIT(1); }
        else                { CP_WAIT(0); }
        __syncthreads();

        const uint32_t baseA = sb + cur * GSTAGE;
        const uint32_t baseB = baseA + TB;

#pragma unroll
        for (int kk = 0; kk < 4; kk++) {
            uint32_t bfr[2][4];
#pragma unroll
            for (int jj = 0; jj < 2; jj++) {
                int rn = wn * 32 + jj * 16 + (lane & 15);
                uint32_t chunk = (uint32_t)(kk * 2 + (lane >> 4));
                uint32_t sw = (uint32_t)(rn * 128) + ((chunk ^ (uint32_t)(rn & 7)) << 4);
                LDSM_X4(bfr[jj][0], bfr[jj][1], bfr[jj][2], bfr[jj][3], baseB + sw);
            }
#pragma unroll
            for (int i = 0; i < 4; i++) {
                int rm = wm * 64 + i * 16 + (lane & 15);
                uint32_t chunk = (uint32_t)(kk * 2 + (lane >> 4));
                uint32_t adr = baseA + (uint32_t)(rm * 128) +
                               ((chunk ^ (uint32_t)(rm & 7)) << 4);
                uint32_t a[4];
                LDSM_X4(a[0], a[1], a[2], a[3], adr);
#pragma unroll
                for (int j = 0; j < 4; j++)
                    MMA_F16(acc.a[i][j], a, bfr[j >> 1][(j & 1)], bfr[j >> 1][(j & 1) + 2]);
            }
        }
        __syncthreads();
    }
}

// QKV projections fused: grid.z selects (A, W slice, bias, out, scale)
__global__ __launch_bounds__(256, 2)
void gemm_qkv(const float* __restrict__ bq, const float* __restrict__ bk,
              const float* __restrict__ bv)
{
    extern __shared__ __align__(128) char sm[];
    const uint32_t sb = smem_u32(sm);
    const int tid = threadIdx.x, wid = tid >> 5, lane = tid & 31;
    const int row0 = blockIdx.y * 128, col0 = blockIdx.x * 128;
    const int z = blockIdx.z;

    const __half* Af = (z == 0) ? g_AQ : (z == 1) ? g_AK : g_AV;
    const __half* Bf = g_W4 + (size_t)z * DMODEL * DMODEL;
    const float* bias = (z == 0) ? bq : (z == 1) ? bk : bv;
    __half* out = (z == 0) ? g_Qf : (z == 1) ? g_Kf : g_Vf;
    const float scale = (z == 0) ? QSCALE : 1.0f;

    GemmAcc acc;
#pragma unroll
    for (int i = 0; i < 4; i++)
#pragma unroll
        for (int j = 0; j < 4; j++)
#pragma unroll
            for (int q = 0; q < 4; q++) acc.a[i][j][q] = 0.0f;

    gemm_mainloop(sb, tid, wid, lane, row0, col0, Af, Bf, acc);

    const int wm = wid >> 2, wn = wid & 3;
#pragma unroll
    for (int i = 0; i < 4; i++) {
#pragma unroll
        for (int j = 0; j < 4; j++) {
            const int m = row0 + wm * 64 + i * 16 + (lane >> 2);
            const int n = col0 + wn * 32 + j * 8 + (lane & 3) * 2;
            float2 bvv = *(const float2*)&bias[n];
            float x0 = (acc.a[i][j][0] + bvv.x) * scale;
            float y0 = (acc.a[i][j][1] + bvv.y) * scale;
            float x1 = (acc.a[i][j][2] + bvv.x) * scale;
            float y1 = (acc.a[i][j][3] + bvv.y) * scale;
            const int b = m >> 11, s = m & 2047;
            const int h = n >> 6,  d = n & 63;
            size_t base = (((size_t)(b * NHEADS + h) * SEQ + s) * DK + d);
            *(uint32_t*)(out + base)          = pack2h(x0, y0);
            *(uint32_t*)(out + base + 8 * DK) = pack2h(x1, y1);
        }
    }
}

// Final output projection: fp32 row-major into d_out
__global__ __launch_bounds__(256, 2)
void gemm_out(const float* __restrict__ bias, float* __restrict__ C)
{
    extern __shared__ __align__(128) char sm[];
    const uint32_t sb = smem_u32(sm);
    const int tid = threadIdx.x, wid = tid >> 5, lane = tid & 31;
    const int row0 = blockIdx.y * 128, col0 = blockIdx.x * 128;

    GemmAcc acc;
#pragma unroll
    for (int i = 0; i < 4; i++)
#pragma unroll
        for (int j = 0; j < 4; j++)
#pragma unroll
            for (int q = 0; q < 4; q++) acc.a[i][j][q] = 0.0f;

    gemm_mainloop(sb, tid, wid, lane, row0, col0, g_Af,
                  g_W4 + (size_t)3 * DMODEL * DMODEL, acc);

    const int wm = wid >> 2, wn = wid & 3;
#pragma unroll
    for (int i = 0; i < 4; i++) {
#pragma unroll
        for (int j = 0; j < 4; j++) {
            const int m = row0 + wm * 64 + i * 16 + (lane >> 2);
            const int n = col0 + wn * 32 + j * 8 + (lane & 3) * 2;
            float2 bvv = *(const float2*)&bias[n];
            *(float2*)&C[(size_t)m * DMODEL + n] =
                make_float2(acc.a[i][j][0] + bvv.x, acc.a[i][j][1] + bvv.y);
            *(float2*)&C[(size_t)(m + 8) * DMODEL + n] =
                make_float2(acc.a[i][j][2] + bvv.x, acc.a[i][j][3] + bvv.y);
        }
    }
}

// ---------------------------------------------------------------------------
// Tensor-core flash attention, no-max softmax:
//   P = exp2(Qf @ Kf^T),  l = rowsum(P) (deferred reduce),  O = P @ Vf / l.
// CTA: 128 queries (8 warps x 16 rows), 64-key tiles, K/V double-buffered.
// ---------------------------------------------------------------------------
#define ASM_BYTES (16384 + 2 * 16384)

__global__ __launch_bounds__(256, 2)
void flash_attn_tc(const int* __restrict__ mask)
{
    extern __shared__ __align__(128) char smA[];
    const uint32_t sb = smem_u32(smA);
    const int tid = threadIdx.x, w = tid >> 5, lane = tid & 31;
    const int qt = blockIdx.x, h = blockIdx.y, b = blockIdx.z;
    const int q0 = qt * 128;

    const size_t bh = (size_t)(b * NHEADS + h);
    const __half* Qfp = g_Qf + (bh * SEQ + q0) * DK;
    const __half* Kfp = g_Kf + bh * SEQ * DK;
    const __half* Vfp = g_Vf + bh * SEQ * DK;

    const uint32_t sQ = sb;

#pragma unroll
    for (int i = 0; i < 4; i++) {
        int cl = tid + 256 * i;
        int r = cl >> 3, c = cl & 7;
        uint32_t sw = (uint32_t)(r * 128) + ((uint32_t)(c ^ (r & 7)) << 4);
        CP_ASYNC16(sQ + sw, Qfp + (size_t)r * DK + c * 8);
    }
    CP_COMMIT();

    auto load_kv = [&](int kt, int stage) {
        const uint32_t base = sb + 16384 + stage * 16384;
        const size_t off = (size_t)(kt * 64) * DK;
        const __half* src[2] = {Kfp + off, Vfp + off};
#pragma unroll
        for (int a = 0; a < 2; a++) {
#pragma unroll
            for (int i = 0; i < 2; i++) {
                int cl = tid + 256 * i;
                int r = cl >> 3, c = cl & 7;
                uint32_t sw = (uint32_t)(r * 128) + ((uint32_t)(c ^ (r & 7)) << 4);
                CP_ASYNC16(base + a * 8192 + sw, src[a] + (size_t)r * DK + c * 8);
            }
        }
        CP_COMMIT();
    };

    load_kv(0, 0);
    CP_WAIT(1);
    __syncthreads();

    uint32_t qf[4][4];
#pragma unroll
    for (int t = 0; t < 4; t++) {
        int r = w * 16 + (lane & 15);
        uint32_t cc = (uint32_t)(t * 2 + (lane >> 4));
        uint32_t sw = (uint32_t)(r * 128) + ((cc ^ (uint32_t)(r & 7)) << 4);
        LDSM_X4(qf[t][0], qf[t][1], qf[t][2], qf[t][3], sQ + sw);
    }

    float o[8][4];
#pragma unroll
    for (int nt = 0; nt < 8; nt++)
#pragma unroll
        for (int q = 0; q < 4; q++) o[nt][q] = 0.0f;
    float l0 = 0.0f, l1 = 0.0f;

    const unsigned char* fl = g_flags + (b * (SEQ / 128) + qt) * (SEQ / 64);
    const int qrow0 = q0 + w * 16 + (lane >> 2);

    for (int kt = 0; kt < SEQ / 64; kt++) {
        const int cur = kt & 1;
        if (kt + 1 < SEQ / 64) { load_kv(kt + 1, cur ^ 1); CP_WAIT(1); }
        else                   { CP_WAIT(0); }
        __syncthreads();

        const uint32_t kvb = sb + 16384 + cur * 16384;
        const uint32_t sKF = kvb, sVF = kvb + 8192;

        // ---- S = Qf @ Kf^T  (log2-scaled) ----
        float s[8][4];
#pragma unroll
        for (int nt = 0; nt < 8; nt++)
#pragma unroll
            for (int q = 0; q < 4; q++) s[nt][q] = 0.0f;

#pragma unroll
        for (int t = 0; t < 4; t++) {
#pragma unroll
            for (int p = 0; p < 4; p++) {
                int kr = p * 16 + (lane & 15);
                uint32_t cc = (uint32_t)(t * 2 + (lane >> 4));
                uint32_t sw = (uint32_t)(kr * 128) + ((cc ^ (uint32_t)(kr & 7)) << 4);
                uint32_t k0, k1, k2, k3;
                LDSM_X4(k0, k1, k2, k3, sKF + sw);
                MMA_F16(s[2 * p],     qf[t], k0, k2);
                MMA_F16(s[2 * p + 1], qf[t], k1, k3);
            }
        }

        if (!fl[kt]) {
            const int* mr0 = mask + ((size_t)b * SEQ + qrow0) * SEQ + kt * 64 + (lane & 3) * 2;
            const int* mr1 = mr0 + 8 * SEQ;
#pragma unroll
            for (int nt = 0; nt < 8; nt++) {
                int2 a = *(const int2*)(mr0 + nt * 8);
                int2 c = *(const int2*)(mr1 + nt * 8);
                if (a.x == 0) s[nt][0] = -1e9f;
                if (a.y == 0) s[nt][1] = -1e9f;
                if (c.x == 0) s[nt][2] = -1e9f;
                if (c.y == 0) s[nt][3] = -1e9f;
            }
        }

        // ---- P = exp2(S); accumulate row sums per-thread ----
#pragma unroll
        for (int nt = 0; nt < 8; nt++) {
            s[nt][0] = exp2f(s[nt][0]);
            s[nt][1] = exp2f(s[nt][1]);
            s[nt][2] = exp2f(s[nt][2]);
            s[nt][3] = exp2f(s[nt][3]);
            l0 += s[nt][0] + s[nt][1];
            l1 += s[nt][2] + s[nt][3];
        }

        // ---- P -> fp16 A-fragments ----
        uint32_t ph[4][4];
#pragma unroll
        for (int kc = 0; kc < 4; kc++) {
            ph[kc][0] = pack2h(s[2 * kc][0],     s[2 * kc][1]);
            ph[kc][1] = pack2h(s[2 * kc][2],     s[2 * kc][3]);
            ph[kc][2] = pack2h(s[2 * kc + 1][0], s[2 * kc + 1][1]);
            ph[kc][3] = pack2h(s[2 * kc + 1][2], s[2 * kc + 1][3]);
        }

        // ---- O += Pf @ Vf ----
        const int g = lane >> 3;
#pragma unroll
        for (int kc = 0; kc < 4; kc++) {
            int vr = kc * 16 + (g & 1) * 8 + (lane & 7);
#pragma unroll
            for (int p = 0; p < 4; p++) {
                uint32_t cc = (uint32_t)(p * 2 + (g >> 1));
                uint32_t sw = (uint32_t)(vr * 128) + ((cc ^ (uint32_t)(vr & 7)) << 4);
                uint32_t v0, v1, v2, v3;
                LDSM_X4_T(v0, v1, v2, v3, sVF + sw);
                MMA_F16(o[2 * p],     ph[kc], v0, v1);
                MMA_F16(o[2 * p + 1], ph[kc], v2, v3);
            }
        }
        __syncthreads();
    }

    // ---- single deferred row-sum reduction ----
    l0 += __shfl_xor_sync(0xffffffffu, l0, 1);
    l0 += __shfl_xor_sync(0xffffffffu, l0, 2);
    l1 += __shfl_xor_sync(0xffffffffu, l1, 1);
    l1 += __shfl_xor_sync(0xffffffffu, l1, 2);

    float inv0 = 1.0f / l0, inv1 = 1.0f / l1;
    size_t rb0 = ((size_t)b * SEQ + qrow0) * DMODEL + h * DK;
#pragma unroll
    for (int nt = 0; nt < 8; nt++) {
        int d = nt * 8 + (lane & 3) * 2;
        *(uint32_t*)(g_Af + rb0 + d) = pack2h(o[nt][0] * inv0, o[nt][1] * inv0);
        *(uint32_t*)(g_Af + rb0 + 8 * DMODEL + d) = pack2h(o[nt][2] * inv1, o[nt][3] * inv1);
    }
}

// ---------------------------------------------------------------------------
extern "C" void kernel_launch(void* const* d_in, const int* in_sizes, int n_in,
                              void* d_out, int out_size)
{
    const float* query = (const float*)d_in[0];
    const float* key   = (const float*)d_in[1];
    const float* value = (const float*)d_in[2];
    const int*   mask  = (const int*)d_in[3];
    const float* Wq = (const float*)d_in[4];
    const float* bq = (const float*)d_in[5];
    const float* Wk = (const float*)d_in[6];
    const float* bk = (const float*)d_in[7];
    const float* Wv = (const float*)d_in[8];
    const float* bv = (const float*)d_in[9];
    const float* Wo = (const float*)d_in[10];
    const float* bo = (const float*)d_in[11];

    const int nact4 = MROWS * DMODEL / 4;    // 2M vec4 -> 8192 blocks
    cudaFuncSetAttribute(gemm_qkv, cudaFuncAttributeMaxDynamicSharedMemorySize, GSMEM);
    cudaFuncSetAttribute(gemm_out, cudaFuncAttributeMaxDynamicSharedMemorySize, GSMEM);
    cudaFuncSetAttribute(flash_attn_tc, cudaFuncAttributeMaxDynamicSharedMemorySize, ASM_BYTES);

    // one fused prep launch: rounds + mask flags
    prep<<<dim3(nact4 / 256, 1, 8), 256>>>(query, key, value, Wq, Wk, Wv, Wo, mask);

    // Q/K/V projections in one launch
    gemm_qkv<<<dim3(DMODEL / 128, MROWS / 128, 3), 256, GSMEM>>>(bq, bk, bv);

    // attention
    flash_attn_tc<<<dim3(SEQ / 128, NHEADS, BATCH), 256, ASM_BYTES>>>(mask);

    // output projection
    gemm_out<<<dim3(DMODEL / 128, MROWS / 128), 256, GSMEM>>>(bo, (float*)d_out);
}

// round 12
// speedup vs baseline: 1.4291x; 1.4291x over previous
#include <cuda_runtime.h>
#include <cuda_fp16.h>
#include <cstdint>

#define BATCH  4
#define SEQ    2048
#define DMODEL 1024
#define NHEADS 16
#define DK     64
#define MROWS  (BATCH * SEQ)   // 8192

// Q prescale: 1/sqrt(64) * log2(e)  (softmax uses exp2)
#define QSCALE 0.18033688f

// ---------------- scratch (device globals; no runtime allocation) ----------
__device__ __half g_Qf[(size_t)MROWS * DMODEL];   // [B,H,S,DK] fp16 (pre-scaled)
__device__ __half g_Kf[(size_t)MROWS * DMODEL];
__device__ __half g_Vf[(size_t)MROWS * DMODEL];
__device__ __half g_AQ[(size_t)MROWS * DMODEL];   // rounded activations per input
__device__ __half g_AK[(size_t)MROWS * DMODEL];
__device__ __half g_AV[(size_t)MROWS * DMODEL];
__device__ __half g_Af[(size_t)MROWS * DMODEL];   // attn output (final GEMM A)
__device__ __half g_W4[(size_t)4 * DMODEL * DMODEL];  // rounded Wq,Wk,Wv,Wo
__device__ unsigned char g_flags[BATCH * (SEQ / 128) * (SEQ / 64)];  // 2048

// ---------------- helpers ---------------------------------------------------
static __device__ __forceinline__ uint32_t smem_u32(const void* p) {
    uint32_t r;
    asm("{ .reg .u64 t; cvta.to.shared.u64 t, %1; cvt.u32.u64 %0, t; }"
        : "=r"(r) : "l"(p));
    return r;
}

#define CP_ASYNC16(smem_addr, gptr) \
    asm volatile("cp.async.cg.shared.global [%0], [%1], 16;" \
                 :: "r"(smem_addr), "l"(gptr))
#define CP_COMMIT()  asm volatile("cp.async.commit_group;" ::: "memory")
#define CP_WAIT(N)   asm volatile("cp.async.wait_group %0;" :: "n"(N) : "memory")

#define LDSM_X4(r0, r1, r2, r3, addr) \
    asm volatile("ldmatrix.sync.aligned.m8n8.x4.shared.b16 {%0,%1,%2,%3}, [%4];" \
                 : "=r"(r0), "=r"(r1), "=r"(r2), "=r"(r3) : "r"(addr))

#define LDSM_X4_T(r0, r1, r2, r3, addr) \
    asm volatile("ldmatrix.sync.aligned.m8n8.x4.trans.shared.b16 {%0,%1,%2,%3}, [%4];" \
                 : "=r"(r0), "=r"(r1), "=r"(r2), "=r"(r3) : "r"(addr))

#define MMA_F16(c, a, b0v, b1v) \
    asm volatile("mma.sync.aligned.m16n8k16.row.col.f32.f16.f16.f32 " \
                 "{%0,%1,%2,%3}, {%4,%5,%6,%7}, {%8,%9}, {%0,%1,%2,%3};" \
                 : "+f"((c)[0]), "+f"((c)[1]), "+f"((c)[2]), "+f"((c)[3]) \
                 : "r"((a)[0]), "r"((a)[1]), "r"((a)[2]), "r"((a)[3]), \
                   "r"(b0v), "r"(b1v))

static __device__ __forceinline__ uint32_t pack2h(float x, float y) {
    __half2 h = __floats2half2_rn(x, y);
    return *(uint32_t*)&h;
}

// ---------------------------------------------------------------------------
// Fused prep: z=0..2 round activations, z=3..6 round weights, z=7 mask flags
// ---------------------------------------------------------------------------
__global__ __launch_bounds__(256)
void prep(const float* __restrict__ q, const float* __restrict__ k,
          const float* __restrict__ v,
          const float* __restrict__ wq, const float* __restrict__ wk,
          const float* __restrict__ wv, const float* __restrict__ wo,
          const int* __restrict__ mask)
{
    const int z = blockIdx.z;
    const int bx = blockIdx.x;

    if (z < 3) {                       // activations: 8192 blocks each
        const float* src = (z == 0) ? q : (z == 1) ? k : v;
        __half* dst = (z == 0) ? g_AQ : (z == 1) ? g_AK : g_AV;
        int i = bx * 256 + threadIdx.x;
        float4 vv = ((const float4*)src)[i];
        ((uint32_t*)dst)[2 * i]     = pack2h(vv.x, vv.y);
        ((uint32_t*)dst)[2 * i + 1] = pack2h(vv.z, vv.w);
    } else if (z < 7) {                // weights: 1024 blocks each
        if (bx >= DMODEL * DMODEL / 4 / 256) return;
        const int wz = z - 3;
        const float* src = (wz == 0) ? wq : (wz == 1) ? wk : (wz == 2) ? wv : wo;
        __half* dst = g_W4 + (size_t)wz * DMODEL * DMODEL;
        int i = bx * 256 + threadIdx.x;
        float4 vv = ((const float4*)src)[i];
        ((uint32_t*)dst)[2 * i]     = pack2h(vv.x, vv.y);
        ((uint32_t*)dst)[2 * i + 1] = pack2h(vv.z, vv.w);
    } else {                           // mask flags: 2048 blocks
        if (bx >= BATCH * (SEQ / 128) * (SEQ / 64)) return;
        const int kt = bx & 31, qt = (bx >> 5) & 15, b = bx >> 9;
        const int tid = threadIdx.x;
        const int qr = tid >> 1, ch = (tid & 1) * 32;
        const int* row = mask + ((size_t)b * SEQ + qt * 128 + qr) * SEQ + kt * 64 + ch;
        int ok = 1;
#pragma unroll
        for (int i = 0; i < 8; i++) {
            int4 mv = *(const int4*)(row + i * 4);
            ok &= (mv.x != 0) & (mv.y != 0) & (mv.z != 0) & (mv.w != 0);
        }
        int all = __syncthreads_and(ok);
        if (tid == 0) g_flags[bx] = (unsigned char)all;
    }
}

// ---------------------------------------------------------------------------
// GEMM core (single fp16 pass): CTA 128x128, K-tile 64, cp.async double buffer.
// ---------------------------------------------------------------------------
#define KTILES 16
#define TB 16384
#define GSTAGE (2 * TB)
#define GSMEM  (2 * GSTAGE)      // 65536

struct GemmAcc { float a[4][4][4]; };

static __device__ __forceinline__ void gemm_mainloop(
    uint32_t sb, int tid, int wid, int lane, int row0, int col0,
    const __half* Af, const __half* Bf, GemmAcc& acc)
{
    const int wm = wid >> 2, wn = wid & 3;

    auto load_tiles = [&](int kt, int stage) {
        const __half* gA = Af + (size_t)row0 * DMODEL + kt * 64;
        const __half* gB = Bf + (size_t)col0 * DMODEL + kt * 64;
        const uint32_t oA = sb + stage * GSTAGE;
#pragma unroll
        for (int i = 0; i < 4; i++) {
            int cl = tid + 256 * i;
            int r  = cl >> 3, c = cl & 7;
            uint32_t sw = (uint32_t)(r * 128) + ((uint32_t)(c ^ (r & 7)) << 4);
            CP_ASYNC16(oA + sw,      gA + (size_t)r * DMODEL + c * 8);
            CP_ASYNC16(oA + TB + sw, gB + (size_t)r * DMODEL + c * 8);
        }
        CP_COMMIT();
    };

    load_tiles(0, 0);

    for (int t = 0; t < KTILES; t++) {
        const int cur = t & 1;
        if (t + 1 < KTILES) { load_tiles(t + 1, cur ^ 1); CP_WAIT(1); }
        else                { CP_WAIT(0); }
        __syncthreads();

        const uint32_t baseA = sb + cur * GSTAGE;
        const uint32_t baseB = baseA + TB;

#pragma unroll
        for (int kk = 0; kk < 4; kk++) {
            uint32_t bfr[2][4];
#pragma unroll
            for (int jj = 0; jj < 2; jj++) {
                int rn = wn * 32 + jj * 16 + (lane & 15);
                uint32_t chunk = (uint32_t)(kk * 2 + (lane >> 4));
                uint32_t sw = (uint32_t)(rn * 128) + ((chunk ^ (uint32_t)(rn & 7)) << 4);
                LDSM_X4(bfr[jj][0], bfr[jj][1], bfr[jj][2], bfr[jj][3], baseB + sw);
            }
#pragma unroll
            for (int i = 0; i < 4; i++) {
                int rm = wm * 64 + i * 16 + (lane & 15);
                uint32_t chunk = (uint32_t)(kk * 2 + (lane >> 4));
                uint32_t adr = baseA + (uint32_t)(rm * 128) +
                               ((chunk ^ (uint32_t)(rm & 7)) << 4);
                uint32_t a[4];
                LDSM_X4(a[0], a[1], a[2], a[3], adr);
#pragma unroll
                for (int j = 0; j < 4; j++)
                    MMA_F16(acc.a[i][j], a, bfr[j >> 1][(j & 1)], bfr[j >> 1][(j & 1) + 2]);
            }
        }
        __syncthreads();
    }
}

// QKV projections fused: grid.z selects (A, W slice, bias, out, scale)
__global__ __launch_bounds__(256)
void gemm_qkv(const float* __restrict__ bq, const float* __restrict__ bk,
              const float* __restrict__ bv)
{
    extern __shared__ __align__(128) char sm[];
    const uint32_t sb = smem_u32(sm);
    const int tid = threadIdx.x, wid = tid >> 5, lane = tid & 31;
    const int row0 = blockIdx.y * 128, col0 = blockIdx.x * 128;
    const int z = blockIdx.z;

    const __half* Af = (z == 0) ? g_AQ : (z == 1) ? g_AK : g_AV;
    const __half* Bf = g_W4 + (size_t)z * DMODEL * DMODEL;
    const float* bias = (z == 0) ? bq : (z == 1) ? bk : bv;
    __half* out = (z == 0) ? g_Qf : (z == 1) ? g_Kf : g_Vf;
    const float scale = (z == 0) ? QSCALE : 1.0f;

    GemmAcc acc;
#pragma unroll
    for (int i = 0; i < 4; i++)
#pragma unroll
        for (int j = 0; j < 4; j++)
#pragma unroll
            for (int q = 0; q < 4; q++) acc.a[i][j][q] = 0.0f;

    gemm_mainloop(sb, tid, wid, lane, row0, col0, Af, Bf, acc);

    const int wm = wid >> 2, wn = wid & 3;
#pragma unroll
    for (int i = 0; i < 4; i++) {
#pragma unroll
        for (int j = 0; j < 4; j++) {
            const int m = row0 + wm * 64 + i * 16 + (lane >> 2);
            const int n = col0 + wn * 32 + j * 8 + (lane & 3) * 2;
            float2 bvv = *(const float2*)&bias[n];
            float x0 = (acc.a[i][j][0] + bvv.x) * scale;
            float y0 = (acc.a[i][j][1] + bvv.y) * scale;
            float x1 = (acc.a[i][j][2] + bvv.x) * scale;
            float y1 = (acc.a[i][j][3] + bvv.y) * scale;
            const int b = m >> 11, s = m & 2047;
            const int h = n >> 6,  d = n & 63;
            size_t base = (((size_t)(b * NHEADS + h) * SEQ + s) * DK + d);
            *(uint32_t*)(out + base)          = pack2h(x0, y0);
            *(uint32_t*)(out + base + 8 * DK) = pack2h(x1, y1);
        }
    }
}

// Final output projection: fp32 row-major into d_out
__global__ __launch_bounds__(256)
void gemm_out(const float* __restrict__ bias, float* __restrict__ C)
{
    extern __shared__ __align__(128) char sm[];
    const uint32_t sb = smem_u32(sm);
    const int tid = threadIdx.x, wid = tid >> 5, lane = tid & 31;
    const int row0 = blockIdx.y * 128, col0 = blockIdx.x * 128;

    GemmAcc acc;
#pragma unroll
    for (int i = 0; i < 4; i++)
#pragma unroll
        for (int j = 0; j < 4; j++)
#pragma unroll
            for (int q = 0; q < 4; q++) acc.a[i][j][q] = 0.0f;

    gemm_mainloop(sb, tid, wid, lane, row0, col0, g_Af,
                  g_W4 + (size_t)3 * DMODEL * DMODEL, acc);

    const int wm = wid >> 2, wn = wid & 3;
#pragma unroll
    for (int i = 0; i < 4; i++) {
#pragma unroll
        for (int j = 0; j < 4; j++) {
            const int m = row0 + wm * 64 + i * 16 + (lane >> 2);
            const int n = col0 + wn * 32 + j * 8 + (lane & 3) * 2;
            float2 bvv = *(const float2*)&bias[n];
            *(float2*)&C[(size_t)m * DMODEL + n] =
                make_float2(acc.a[i][j][0] + bvv.x, acc.a[i][j][1] + bvv.y);
            *(float2*)&C[(size_t)(m + 8) * DMODEL + n] =
                make_float2(acc.a[i][j][2] + bvv.x, acc.a[i][j][3] + bvv.y);
        }
    }
}

// ---------------------------------------------------------------------------
// Tensor-core flash attention, no-max softmax:
//   P = exp2(Qf @ Kf^T),  l = rowsum(P) (deferred reduce),  O = P @ Vf / l.
// CTA: 128 queries (8 warps x 16 rows), 64-key tiles, K/V double-buffered.
// ---------------------------------------------------------------------------
#define ASM_BYTES (16384 + 2 * 16384)

__global__ __launch_bounds__(256)
void flash_attn_tc(const int* __restrict__ mask)
{
    extern __shared__ __align__(128) char smA[];
    const uint32_t sb = smem_u32(smA);
    const int tid = threadIdx.x, w = tid >> 5, lane = tid & 31;
    const int qt = blockIdx.x, h = blockIdx.y, b = blockIdx.z;
    const int q0 = qt * 128;

    const size_t bh = (size_t)(b * NHEADS + h);
    const __half* Qfp = g_Qf + (bh * SEQ + q0) * DK;
    const __half* Kfp = g_Kf + bh * SEQ * DK;
    const __half* Vfp = g_Vf + bh * SEQ * DK;

    const uint32_t sQ = sb;

#pragma unroll
    for (int i = 0; i < 4; i++) {
        int cl = tid + 256 * i;
        int r = cl >> 3, c = cl & 7;
        uint32_t sw = (uint32_t)(r * 128) + ((uint32_t)(c ^ (r & 7)) << 4);
        CP_ASYNC16(sQ + sw, Qfp + (size_t)r * DK + c * 8);
    }
    CP_COMMIT();

    auto load_kv = [&](int kt, int stage) {
        const uint32_t base = sb + 16384 + stage * 16384;
        const size_t off = (size_t)(kt * 64) * DK;
        const __half* src[2] = {Kfp + off, Vfp + off};
#pragma unroll
        for (int a = 0; a < 2; a++) {
#pragma unroll
            for (int i = 0; i < 2; i++) {
                int cl = tid + 256 * i;
                int r = cl >> 3, c = cl & 7;
                uint32_t sw = (uint32_t)(r * 128) + ((uint32_t)(c ^ (r & 7)) << 4);
                CP_ASYNC16(base + a * 8192 + sw, src[a] + (size_t)r * DK + c * 8);
            }
        }
        CP_COMMIT();
    };

    load_kv(0, 0);
    CP_WAIT(1);
    __syncthreads();

    uint32_t qf[4][4];
#pragma unroll
    for (int t = 0; t < 4; t++) {
        int r = w * 16 + (lane & 15);
        uint32_t cc = (uint32_t)(t * 2 + (lane >> 4));
        uint32_t sw = (uint32_t)(r * 128) + ((cc ^ (uint32_t)(r & 7)) << 4);
        LDSM_X4(qf[t][0], qf[t][1], qf[t][2], qf[t][3], sQ + sw);
    }

    float o[8][4];
#pragma unroll
    for (int nt = 0; nt < 8; nt++)
#pragma unroll
        for (int q = 0; q < 4; q++) o[nt][q] = 0.0f;
    float l0 = 0.0f, l1 = 0.0f;

    const unsigned char* fl = g_flags + (b * (SEQ / 128) + qt) * (SEQ / 64);
    const int qrow0 = q0 + w * 16 + (lane >> 2);

    for (int kt = 0; kt < SEQ / 64; kt++) {
        const int cur = kt & 1;
        if (kt + 1 < SEQ / 64) { load_kv(kt + 1, cur ^ 1); CP_WAIT(1); }
        else                   { CP_WAIT(0); }
        __syncthreads();

        const uint32_t kvb = sb + 16384 + cur * 16384;
        const uint32_t sKF = kvb, sVF = kvb + 8192;

        // ---- S = Qf @ Kf^T  (log2-scaled) ----
        float s[8][4];
#pragma unroll
        for (int nt = 0; nt < 8; nt++)
#pragma unroll
            for (int q = 0; q < 4; q++) s[nt][q] = 0.0f;

#pragma unroll
        for (int t = 0; t < 4; t++) {
#pragma unroll
            for (int p = 0; p < 4; p++) {
                int kr = p * 16 + (lane & 15);
                uint32_t cc = (uint32_t)(t * 2 + (lane >> 4));
                uint32_t sw = (uint32_t)(kr * 128) + ((cc ^ (uint32_t)(kr & 7)) << 4);
                uint32_t k0, k1, k2, k3;
                LDSM_X4(k0, k1, k2, k3, sKF + sw);
                MMA_F16(s[2 * p],     qf[t], k0, k2);
                MMA_F16(s[2 * p + 1], qf[t], k1, k3);
            }
        }

        if (!fl[kt]) {
            const int* mr0 = mask + ((size_t)b * SEQ + qrow0) * SEQ + kt * 64 + (lane & 3) * 2;
            const int* mr1 = mr0 + 8 * SEQ;
#pragma unroll
            for (int nt = 0; nt < 8; nt++) {
                int2 a = *(const int2*)(mr0 + nt * 8);
                int2 c = *(const int2*)(mr1 + nt * 8);
                if (a.x == 0) s[nt][0] = -1e9f;
                if (a.y == 0) s[nt][1] = -1e9f;
                if (c.x == 0) s[nt][2] = -1e9f;
                if (c.y == 0) s[nt][3] = -1e9f;
            }
        }

        // ---- P = exp2(S); accumulate row sums per-thread ----
#pragma unroll
        for (int nt = 0; nt < 8; nt++) {
            s[nt][0] = exp2f(s[nt][0]);
            s[nt][1] = exp2f(s[nt][1]);
            s[nt][2] = exp2f(s[nt][2]);
            s[nt][3] = exp2f(s[nt][3]);
            l0 += s[nt][0] + s[nt][1];
            l1 += s[nt][2] + s[nt][3];
        }

        // ---- P -> fp16 A-fragments ----
        uint32_t ph[4][4];
#pragma unroll
        for (int kc = 0; kc < 4; kc++) {
            ph[kc][0] = pack2h(s[2 * kc][0],     s[2 * kc][1]);
            ph[kc][1] = pack2h(s[2 * kc][2],     s[2 * kc][3]);
            ph[kc][2] = pack2h(s[2 * kc + 1][0], s[2 * kc + 1][1]);
            ph[kc][3] = pack2h(s[2 * kc + 1][2], s[2 * kc + 1][3]);
        }

        // ---- O += Pf @ Vf ----
        const int g = lane >> 3;
#pragma unroll
        for (int kc = 0; kc < 4; kc++) {
            int vr = kc * 16 + (g & 1) * 8 + (lane & 7);
#pragma unroll
            for (int p = 0; p < 4; p++) {
                uint32_t cc = (uint32_t)(p * 2 + (g >> 1));
                uint32_t sw = (uint32_t)(vr * 128) + ((cc ^ (uint32_t)(vr & 7)) << 4);
                uint32_t v0, v1, v2, v3;
                LDSM_X4_T(v0, v1, v2, v3, sVF + sw);
                MMA_F16(o[2 * p],     ph[kc], v0, v1);
                MMA_F16(o[2 * p + 1], ph[kc], v2, v3);
            }
        }
        __syncthreads();
    }

    // ---- single deferred row-sum reduction ----
    l0 += __shfl_xor_sync(0xffffffffu, l0, 1);
    l0 += __shfl_xor_sync(0xffffffffu, l0, 2);
    l1 += __shfl_xor_sync(0xffffffffu, l1, 1);
    l1 += __shfl_xor_sync(0xffffffffu, l1, 2);

    float inv0 = 1.0f / l0, inv1 = 1.0f / l1;
    size_t rb0 = ((size_t)b * SEQ + qrow0) * DMODEL + h * DK;
#pragma unroll
    for (int nt = 0; nt < 8; nt++) {
        int d = nt * 8 + (lane & 3) * 2;
        *(uint32_t*)(g_Af + rb0 + d) = pack2h(o[nt][0] * inv0, o[nt][1] * inv0);
        *(uint32_t*)(g_Af + rb0 + 8 * DMODEL + d) = pack2h(o[nt][2] * inv1, o[nt][3] * inv1);
    }
}

// ---------------------------------------------------------------------------
extern "C" void kernel_launch(void* const* d_in, const int* in_sizes, int n_in,
                              void* d_out, int out_size)
{
    const float* query = (const float*)d_in[0];
    const float* key   = (const float*)d_in[1];
    const float* value = (const float*)d_in[2];
    const int*   mask  = (const int*)d_in[3];
    const float* Wq = (const float*)d_in[4];
    const float* bq = (const float*)d_in[5];
    const float* Wk = (const float*)d_in[6];
    const float* bk = (const float*)d_in[7];
    const float* Wv = (const float*)d_in[8];
    const float* bv = (const float*)d_in[9];
    const float* Wo = (const float*)d_in[10];
    const float* bo = (const float*)d_in[11];

    const int nact4 = MROWS * DMODEL / 4;    // 2M vec4 -> 8192 blocks
    cudaFuncSetAttribute(gemm_qkv, cudaFuncAttributeMaxDynamicSharedMemorySize, GSMEM);
    cudaFuncSetAttribute(gemm_out, cudaFuncAttributeMaxDynamicSharedMemorySize, GSMEM);
    cudaFuncSetAttribute(flash_attn_tc, cudaFuncAttributeMaxDynamicSharedMemorySize, ASM_BYTES);

    // one fused prep launch: rounds + mask flags
    prep<<<dim3(nact4 / 256, 1, 8), 256>>>(query, key, value, Wq, Wk, Wv, Wo, mask);

    // Q/K/V projections in one launch
    gemm_qkv<<<dim3(DMODEL / 128, MROWS / 128, 3), 256, GSMEM>>>(bq, bk, bv);

    // attention
    flash_attn_tc<<<dim3(SEQ / 128, NHEADS, BATCH), 256, ASM_BYTES>>>(mask);

    // output projection
    gemm_out<<<dim3(DMODEL / 128, MROWS / 128), 256, GSMEM>>>(bo, (float*)d_out);
}